// round 3
// baseline (speedup 1.0000x reference)
#include <cuda_runtime.h>
#include <math.h>

#define NV 32768
#define EV 512
#define DV 32
#define CV 50
#define H3V 281

// ---------------- device scratch (static, no allocation) ----------------
__device__ float g_bufA[NV * EV];          // h1, reused for h3 (ld=281)
__device__ float g_bufB[NV * EV];          // h2
__device__ float g_logits[NV * CV];
__device__ float g_gumbel[NV * CV];        // rows 0..NV-2 used
__device__ float g_plog[NV * CV];          // per-step permuted logits
__device__ int   g_padj[NV * DV];          // per-step permuted adjacency
__device__ float g_terms[NV];
__device__ int   g_colors[NV];
__device__ int   g_pos[NV];
__device__ int   g_viol;

// ---------------- helpers ----------------
__device__ __forceinline__ unsigned fenc(float f) {
    unsigned u = __float_as_uint(f);
    return (u & 0x80000000u) ? ~u : (u | 0x80000000u);
}
__device__ __forceinline__ float fdec(unsigned u) {
    return (u & 0x80000000u) ? __uint_as_float(u ^ 0x80000000u)
                             : __uint_as_float(~u);
}
__device__ __forceinline__ unsigned rotl32(unsigned x, int r) {
    return (x << r) | (x >> (32 - r));
}

// ---------------- GEMM: C = act(A[M,K] @ B[K,Nc] + bias) ----------------
// Accumulation per output element is strictly sequential in k (ascending),
// single fp32 FMA accumulator from 0, bias added after, leaky applied last.
// This matches XLA's loop-emitter gemv evaluation order as closely as possible.
template<int BM, int BN, int BK, int TM, int TN>
__global__ void __launch_bounds__(256) gemm_kernel(
    const float* __restrict__ A, const float* __restrict__ B,
    const float* __restrict__ bias, float* __restrict__ C,
    int M, int K, int Nc, int lda, int ldc, int act)
{
    __shared__ float As[BK][BM];
    __shared__ float Bs[BK][BN];
    const int tid = threadIdx.x;
    const int TCOLS = BN / TN;
    const int tr = tid / TCOLS, tc = tid % TCOLS;
    const int rowBase = blockIdx.y * BM;
    const int colBase = blockIdx.x * BN;
    float acc[TM][TN] = {};
    for (int kt = 0; kt < K; kt += BK) {
        for (int e = tid; e < BM * BK; e += 256) {
            int r = e / BK, c = e % BK;
            int kk = kt + c;
            As[c][r] = (kk < K) ? A[(size_t)(rowBase + r) * lda + kk] : 0.f;
        }
        for (int e = tid; e < BK * BN; e += 256) {
            int r = e / BN, c = e % BN;
            int kk = kt + r, cc = colBase + c;
            Bs[r][c] = (kk < K && cc < Nc) ? B[(size_t)kk * Nc + cc] : 0.f;
        }
        __syncthreads();
#pragma unroll
        for (int k = 0; k < BK; k++) {
            float ra[TM], rb[TN];
#pragma unroll
            for (int i = 0; i < TM; i++) ra[i] = As[k][tr * TM + i];
#pragma unroll
            for (int j = 0; j < TN; j++) rb[j] = Bs[k][tc * TN + j];
#pragma unroll
            for (int i = 0; i < TM; i++)
#pragma unroll
                for (int j = 0; j < TN; j++)
                    acc[i][j] = fmaf(ra[i], rb[j], acc[i][j]);
        }
        __syncthreads();
    }
#pragma unroll
    for (int i = 0; i < TM; i++) {
        int r = rowBase + tr * TM + i;
#pragma unroll
        for (int j = 0; j < TN; j++) {
            int cidx = colBase + tc * TN + j;
            if (cidx < Nc) {
                float v = acc[i][j] + bias[cidx];
                if (act) v = (v >= 0.f) ? v : 0.01f * v;
                C[(size_t)r * ldc + cidx] = v;
            }
        }
    }
}

// ---------------- gumbel via PARTITIONABLE Threefry-2x32 (jax >= 0.4.36) --
// For 32-bit draws with jax_threefry_partitionable=True (the modern default):
//   counter = uint64 iota; element i uses x = (hi32(i), lo32(i)) = (0, i)
//   bits[i] = out0 ^ out1 of threefry2x32(key=(0,42), x)
// Then u = max(tiny, bitcast(bits>>9 | 0x3f800000) - 1), g = -log(-log(u))
// computed with fp32 logf (libdevice __nv_logf, same as XLA's GPU lowering).
__global__ void gumbel_kernel()
{
    const int total = (NV - 1) * CV;
    int i = blockIdx.x * blockDim.x + threadIdx.x;
    if (i >= total) return;
    unsigned x0 = 0u;              // counts_hi (i < 2^32)
    unsigned x1 = (unsigned)i;     // counts_lo
    const unsigned k0 = 0u, k1 = 42u, k2 = 0u ^ 42u ^ 0x1BD11BDAu;
    x0 += k0; x1 += k1;
#define TFR(r) { x0 += x1; x1 = rotl32(x1, r); x1 ^= x0; }
    TFR(13) TFR(15) TFR(26) TFR(6)  x0 += k1; x1 += k2 + 1u;
    TFR(17) TFR(29) TFR(16) TFR(24) x0 += k2; x1 += k0 + 2u;
    TFR(13) TFR(15) TFR(26) TFR(6)  x0 += k0; x1 += k1 + 3u;
    TFR(17) TFR(29) TFR(16) TFR(24) x0 += k1; x1 += k2 + 4u;
    TFR(13) TFR(15) TFR(26) TFR(6)  x0 += k2; x1 += k0 + 5u;
#undef TFR
    unsigned bits = x0 ^ x1;       // partitionable 32-bit draw
    unsigned fb = (bits >> 9) | 0x3f800000u;
    float f = __uint_as_float(fb) - 1.0f;           // [0,1)
    const float tiny = 1.17549435e-38f;
    float u = fmaxf(tiny, f + tiny);                // == max(tiny, f*(1-tiny)+tiny)
    g_gumbel[i] = -logf(-logf(u));                  // fp32, libdevice-matching
}

// ---------------- pos scatter + counter reset ----------------
__global__ void pos_kernel(const int* __restrict__ vorder)
{
    int i = blockIdx.x * blockDim.x + threadIdx.x;
    if (i < NV) g_pos[vorder[i]] = i;
    if (i == 0) g_viol = 0;
}

// ---------------- pre-gather per-step data (kills dependent-load chain) --
__global__ void prep_kernel(const int* __restrict__ vorder,
                            const int* __restrict__ adj)
{
    int warp = (blockIdx.x * blockDim.x + threadIdx.x) >> 5;
    int lane = threadIdx.x & 31;
    int t = warp + 1;
    if (t >= NV) return;
    int v = vorder[t];
    g_padj[t * DV + lane] = adj[v * DV + lane];
    g_plog[t * CV + lane] = g_logits[v * CV + lane];
    if (lane + 32 < CV)
        g_plog[t * CV + lane + 32] = g_logits[v * CV + lane + 32];
}

// ---------------- sequential scan (single warp, colors in SMEM) ----------
// EXACT argmax semantics: full 32-bit monotone float compare, then lowest
// color index among holders of the max (matches jnp.argmax tie rule).
__device__ __forceinline__ void do_step(int* colS, int lane, int v, int adjv,
                                        float l0, float l1, float g0, float g1,
                                        bool ok1, int c1)
{
    int ncol = colS[adjv];
    unsigned lo = 0u, hi = 0u;
    if (ncol >= 0) {
        if (ncol < 32) lo = 1u << ncol; else hi = 1u << (ncol - 32);
    }
    lo = __reduce_or_sync(0xffffffffu, lo);
    hi = __reduce_or_sync(0xffffffffu, hi);
    const float NEGINF = __int_as_float((int)0xff800000);
    float s0 = ((lo >> lane) & 1u) ? NEGINF : (l0 + g0);
    float s1 = (ok1 && !((hi >> lane) & 1u)) ? (l1 + g1) : NEGINF;
    float s; int idx;
    if (s1 > s0) { s = s1; idx = c1; } else { s = s0; idx = lane; }
    unsigned e = fenc(s);
    unsigned m = __reduce_max_sync(0xffffffffu, e);
    unsigned ic = (e == m) ? (unsigned)idx : 64u;
    int chosen = (int)__reduce_min_sync(0xffffffffu, ic);
    if (lane == 0) { colS[v] = chosen; g_colors[v] = chosen; }
    __syncwarp();
}

__global__ void __launch_bounds__(32, 1) scan_kernel(const int* __restrict__ vorder)
{
    extern __shared__ int colS[];
    const int lane = threadIdx.x;
    for (int i = lane; i < NV; i += 32) colS[i] = -1;
    __syncwarp();
    int v0 = vorder[0];
    if (lane == 0) { colS[v0] = 0; g_colors[v0] = 0; }
    __syncwarp();
    const int c1 = lane + 32;
    const bool ok1 = (c1 < CV);

#define LOADSTAGE(tt, V, Aa, L0, L1, G0, G1) {                          \
        int tcl = ((tt) < NV) ? (tt) : (NV - 1);                        \
        V  = vorder[tcl];                                               \
        Aa = g_padj[tcl * DV + lane];                                   \
        L0 = g_plog[tcl * CV + lane];                                   \
        L1 = ok1 ? g_plog[tcl * CV + c1] : 0.f;                         \
        G0 = g_gumbel[(tcl - 1) * CV + lane];                           \
        G1 = ok1 ? g_gumbel[(tcl - 1) * CV + c1] : 0.f; }

    int vA, aA, vB, aB;
    float lA0, lA1, gA0, gA1, lB0, lB1, gB0, gB1;
    LOADSTAGE(1, vA, aA, lA0, lA1, gA0, gA1);
    LOADSTAGE(2, vB, aB, lB0, lB1, gB0, gB1);

    for (int t = 1; t < NV; t += 2) {
        int vN, aN; float n0, n1, n2, n3;
        LOADSTAGE(t + 2, vN, aN, n0, n1, n2, n3);
        do_step(colS, lane, vA, aA, lA0, lA1, gA0, gA1, ok1, c1);
        vA = vN; aA = aN; lA0 = n0; lA1 = n1; gA0 = n2; gA1 = n3;
        if (t + 1 < NV) {
            LOADSTAGE(t + 3, vN, aN, n0, n1, n2, n3);
            do_step(colS, lane, vB, aB, lB0, lB1, gB0, gB1, ok1, c1);
            vB = vN; aB = aN; lB0 = n0; lB1 = n1; gB0 = n2; gB1 = n3;
        }
    }
#undef LOADSTAGE
}

// ---------------- violation count ----------------
__global__ void viol_kernel(const int* __restrict__ adj)
{
    int i = blockIdx.x * blockDim.x + threadIdx.x;
    int c = 0;
    if (i < NV * DV) {
        int n = i >> 5;            // DV == 32
        c = (g_colors[adj[i]] == g_colors[n]) ? 1 : 0;
    }
    c = __reduce_add_sync(0xffffffffu, c);
    if ((threadIdx.x & 31) == 0 && c) atomicAdd(&g_viol, c);
}

// ---------------- parallel logp term reconstruction ----------------
__global__ void terms_kernel(const int* __restrict__ vorder,
                             const int* __restrict__ adj)
{
    int warp = (blockIdx.x * blockDim.x + threadIdx.x) >> 5;
    int lane = threadIdx.x & 31;
    int t = warp + 1;
    if (t >= NV) return;
    int v = vorder[t];
    int nb = adj[v * DV + lane];
    int cn = g_colors[nb];
    int pn = g_pos[nb];
    unsigned lo = 0u, hi = 0u;
    if (pn < t) {                         // assigned strictly before step t
        if (cn < 32) lo = 1u << cn; else hi = 1u << (cn - 32);
    }
    lo = __reduce_or_sync(0xffffffffu, lo);
    hi = __reduce_or_sync(0xffffffffu, hi);
    const float NEGINF = __int_as_float((int)0xff800000);
    float l0 = g_logits[v * CV + lane];
    bool m0 = (lo >> lane) & 1u;
    bool has1 = (lane + 32) < CV;
    float l1 = has1 ? g_logits[v * CV + lane + 32] : 0.f;
    bool m1 = (!has1) || ((hi >> lane) & 1u);
    float mx = fmaxf(m0 ? NEGINF : l0, m1 ? NEGINF : l1);
    mx = fdec(__reduce_max_sync(0xffffffffu, fenc(mx)));
    float e = (m0 ? 0.f : expf(l0 - mx)) + (m1 ? 0.f : expf(l1 - mx));
#pragma unroll
    for (int o = 16; o; o >>= 1) e += __shfl_xor_sync(0xffffffffu, e, o);
    if (lane == 0) {
        int ch = g_colors[v];
        float lc = g_logits[v * CV + ch];
        float prob = expf(lc - mx) / e;
        g_terms[t] = logf(prob + 1e-8f) + 18.420680743952367f; // -log(1e-8)
    }
}

// ---------------- output ----------------
__global__ void colors_out_kernel(float* out)
{
    int i = blockIdx.x * blockDim.x + threadIdx.x;
    if (i < NV) out[i] = (float)g_colors[i];
}

__global__ void final_kernel(float* out, int mode)
{
    const int tid = threadIdx.x;
    float s = 0.f;
    for (int t = 1 + tid; t < NV; t += 1024) s += g_terms[t];
    unsigned long long um = 0ull;
    for (int i = tid; i < NV; i += 1024) um |= (1ull << (g_colors[i] & 63));
#pragma unroll
    for (int o = 16; o; o >>= 1) {
        s  += __shfl_xor_sync(0xffffffffu, s, o);
        um |= __shfl_xor_sync(0xffffffffu, um, o);
    }
    __shared__ float ws[32];
    __shared__ unsigned long long wm[32];
    int w = tid >> 5, l = tid & 31;
    if (l == 0) { ws[w] = s; wm[w] = um; }
    __syncthreads();
    if (tid == 0) {
        float tot = 0.f; unsigned long long m = 0ull;
        for (int i = 0; i < 32; i++) { tot += ws[i]; m |= wm[i]; }
        float confidence = tot / (float)NV;
        int nused = __popcll(m);
        float ratio = (float)g_viol / (float)(NV * DV);
        float cost = (float)nused + ratio * 100.0f;
        float loss = cost * confidence;
        if (mode == 0) out[NV] = loss;
        else           out[0]  = loss;
    }
}

// ---------------- host ----------------
extern "C" void kernel_launch(void* const* d_in, const int* in_sizes, int n_in,
                              void* d_out, int out_size)
{
    const float *emb = 0, *W1 = 0, *b1 = 0, *W2 = 0, *b2 = 0,
                *W3 = 0, *b3 = 0, *W4 = 0, *b4 = 0;
    const int *adj = 0, *vorder = 0;
    for (int i = 0; i < n_in; i++) {
        long s = in_sizes[i];
        void* p = d_in[i];
        if      (s == (long)NV * EV)  emb = (const float*)p;
        else if (s == (long)NV * DV)  adj = (const int*)p;
        else if (s == NV)             vorder = (const int*)p;
        else if (s == (long)EV * EV)  { if (!W1) W1 = (const float*)p; else W2 = (const float*)p; }
        else if (s == EV)             { if (!b1) b1 = (const float*)p; else b2 = (const float*)p; }
        else if (s == (long)EV * H3V) W3 = (const float*)p;
        else if (s == H3V)            b3 = (const float*)p;
        else if (s == (long)H3V * CV) W4 = (const float*)p;
        else if (s == CV)             b4 = (const float*)p;
    }
    if (!emb || !adj || !vorder || !W1 || !b1 || !W2 || !b2 || !W3 || !b3 || !W4 || !b4)
        return;

    float *h1, *h2, *logits;
    cudaGetSymbolAddress((void**)&h1, g_bufA);
    cudaGetSymbolAddress((void**)&h2, g_bufB);
    cudaGetSymbolAddress((void**)&logits, g_logits);

    dim3 blk(256);
    gemm_kernel<128,64,16,8,4><<<dim3(EV / 64, NV / 128), blk>>>(
        emb, W1, b1, h1, NV, EV, EV, EV, EV, 1);
    gemm_kernel<128,64,16,8,4><<<dim3(EV / 64, NV / 128), blk>>>(
        h1, W2, b2, h2, NV, EV, EV, EV, EV, 1);
    gemm_kernel<128,64,16,8,4><<<dim3((H3V + 63) / 64, NV / 128), blk>>>(
        h2, W3, b3, h1, NV, EV, H3V, EV, H3V, 1);
    gemm_kernel<128,64,16,8,4><<<dim3(1, NV / 128), blk>>>(
        h1, W4, b4, logits, NV, H3V, CV, H3V, CV, 0);

    gumbel_kernel<<<((NV - 1) * CV + 255) / 256, 256>>>();
    pos_kernel<<<(NV + 255) / 256, 256>>>(vorder);
    prep_kernel<<<(NV * 32 + 255) / 256, 256>>>(vorder, adj);

    cudaFuncSetAttribute(scan_kernel,
                         cudaFuncAttributeMaxDynamicSharedMemorySize,
                         NV * (int)sizeof(int));
    scan_kernel<<<1, 32, NV * sizeof(int)>>>(vorder);

    viol_kernel<<<(NV * DV + 255) / 256, 256>>>(adj);
    terms_kernel<<<(NV * 32 + 255) / 256, 256>>>(vorder, adj);

    float* outF = (float*)d_out;
    if (out_size >= NV)
        colors_out_kernel<<<(NV + 255) / 256, 256>>>(outF);
    int mode = (out_size >= NV + 1) ? 0 : ((out_size < NV) ? 1 : 2);
    if (mode != 2)
        final_kernel<<<1, 1024>>>(outF, mode);
}

// round 4
// speedup vs baseline: 4.6082x; 4.6082x over previous
#include <cuda_runtime.h>
#include <math.h>

#define NV 32768
#define EV 512
#define DV 32
#define CV 50
#define H3V 281

// ---------------- device scratch (static, no allocation) ----------------
__device__ float g_bufA[NV * EV];          // h1, reused for h3 (ld=281)
__device__ float g_bufB[NV * EV];          // h2
__device__ float g_logits[NV * CV];
__device__ float g_gumbel[NV * CV];        // rows 0..NV-2 used
__device__ float g_terms[NV];
__device__ int   g_colors[NV];
__device__ int   g_pos[NV];
__device__ int   g_viol;

// ---------------- helpers ----------------
__device__ __forceinline__ unsigned fenc(float f) {
    unsigned u = __float_as_uint(f);
    return (u & 0x80000000u) ? ~u : (u | 0x80000000u);
}
__device__ __forceinline__ float fdec(unsigned u) {
    return (u & 0x80000000u) ? __uint_as_float(u ^ 0x80000000u)
                             : __uint_as_float(~u);
}
__device__ __forceinline__ unsigned rotl32(unsigned x, int r) {
    return (x << r) | (x >> (32 - r));
}

// ---------------- GEMM: C = act(A[M,K] @ B[K,Nc] + bias) ----------------
// UNCHANGED from the passing round (accumulation order is semantics-bearing).
template<int BM, int BN, int BK, int TM, int TN>
__global__ void __launch_bounds__(256) gemm_kernel(
    const float* __restrict__ A, const float* __restrict__ B,
    const float* __restrict__ bias, float* __restrict__ C,
    int M, int K, int Nc, int lda, int ldc, int act)
{
    __shared__ float As[BK][BM];
    __shared__ float Bs[BK][BN];
    const int tid = threadIdx.x;
    const int TCOLS = BN / TN;
    const int tr = tid / TCOLS, tc = tid % TCOLS;
    const int rowBase = blockIdx.y * BM;
    const int colBase = blockIdx.x * BN;
    float acc[TM][TN] = {};
    for (int kt = 0; kt < K; kt += BK) {
        for (int e = tid; e < BM * BK; e += 256) {
            int r = e / BK, c = e % BK;
            int kk = kt + c;
            As[c][r] = (kk < K) ? A[(size_t)(rowBase + r) * lda + kk] : 0.f;
        }
        for (int e = tid; e < BK * BN; e += 256) {
            int r = e / BN, c = e % BN;
            int kk = kt + r, cc = colBase + c;
            Bs[r][c] = (kk < K && cc < Nc) ? B[(size_t)kk * Nc + cc] : 0.f;
        }
        __syncthreads();
#pragma unroll
        for (int k = 0; k < BK; k++) {
            float ra[TM], rb[TN];
#pragma unroll
            for (int i = 0; i < TM; i++) ra[i] = As[k][tr * TM + i];
#pragma unroll
            for (int j = 0; j < TN; j++) rb[j] = Bs[k][tc * TN + j];
#pragma unroll
            for (int i = 0; i < TM; i++)
#pragma unroll
                for (int j = 0; j < TN; j++)
                    acc[i][j] = fmaf(ra[i], rb[j], acc[i][j]);
        }
        __syncthreads();
    }
#pragma unroll
    for (int i = 0; i < TM; i++) {
        int r = rowBase + tr * TM + i;
#pragma unroll
        for (int j = 0; j < TN; j++) {
            int cidx = colBase + tc * TN + j;
            if (cidx < Nc) {
                float v = acc[i][j] + bias[cidx];
                if (act) v = (v >= 0.f) ? v : 0.01f * v;
                C[(size_t)r * ldc + cidx] = v;
            }
        }
    }
}

// ---------------- gumbel via PARTITIONABLE Threefry-2x32 (UNCHANGED) -----
__global__ void gumbel_kernel()
{
    const int total = (NV - 1) * CV;
    int i = blockIdx.x * blockDim.x + threadIdx.x;
    if (i >= total) return;
    unsigned x0 = 0u;
    unsigned x1 = (unsigned)i;
    const unsigned k0 = 0u, k1 = 42u, k2 = 0u ^ 42u ^ 0x1BD11BDAu;
    x0 += k0; x1 += k1;
#define TFR(r) { x0 += x1; x1 = rotl32(x1, r); x1 ^= x0; }
    TFR(13) TFR(15) TFR(26) TFR(6)  x0 += k1; x1 += k2 + 1u;
    TFR(17) TFR(29) TFR(16) TFR(24) x0 += k2; x1 += k0 + 2u;
    TFR(13) TFR(15) TFR(26) TFR(6)  x0 += k0; x1 += k1 + 3u;
    TFR(17) TFR(29) TFR(16) TFR(24) x0 += k1; x1 += k2 + 4u;
    TFR(13) TFR(15) TFR(26) TFR(6)  x0 += k2; x1 += k0 + 5u;
#undef TFR
    unsigned bits = x0 ^ x1;
    unsigned fb = (bits >> 9) | 0x3f800000u;
    float f = __uint_as_float(fb) - 1.0f;
    const float tiny = 1.17549435e-38f;
    float u = fmaxf(tiny, f + tiny);
    g_gumbel[i] = -logf(-logf(u));
}

// ---------------- pos scatter + colors init + counter reset --------------
__global__ void pos_kernel(const int* __restrict__ vorder)
{
    int i = blockIdx.x * blockDim.x + threadIdx.x;
    if (i < NV) {
        g_pos[vorder[i]] = i;
        g_colors[i] = -1;
    }
    if (i == 0) g_viol = 0;
}

// ---------------- wavefront dataflow scan --------------------------------
// One warp per step t; dependency = actual DAG edge (neighbor assigned
// earlier). Color word doubles as ready flag (-1 = unassigned). All blocks
// guaranteed co-resident (grid=148, 1024 thr/blk), static increasing step
// assignment per warp => waits are acyclic => guaranteed progress.
#define SCAN_BLOCKS 148
#define SCAN_TPB    1024
#define SCAN_WARPS  (SCAN_BLOCKS * (SCAN_TPB / 32))

__global__ void __launch_bounds__(SCAN_TPB) wavescan_kernel(
    const int* __restrict__ vorder, const int* __restrict__ adj)
{
    const unsigned FULL = 0xffffffffu;
    const int lane = threadIdx.x & 31;
    const int w = (blockIdx.x * SCAN_TPB + threadIdx.x) >> 5;
    volatile int* vcol = g_colors;

    if (w == 0 && lane == 0) {
        vcol[vorder[0]] = 0;               // first vertex gets color 0
    }

    const int c1 = lane + 32;
    const bool ok1 = (c1 < CV);
    const float NEGINF = __int_as_float((int)0xff800000);

    for (int t = 1 + w; t < NV; t += SCAN_WARPS) {
        int v  = vorder[t];
        int nb = adj[v * DV + lane];
        int pn = g_pos[nb];
        float l0 = g_logits[v * CV + lane];
        float l1 = ok1 ? g_logits[v * CV + c1] : 0.f;
        float g0 = g_gumbel[(t - 1) * CV + lane];
        float g1 = ok1 ? g_gumbel[(t - 1) * CV + c1] : 0.f;

        // wait for earlier-assigned neighbors
        bool need = (pn < t);
        int cn = -1;
        int spins = 0;
        while (__any_sync(FULL, need && cn < 0)) {
            if (need && cn < 0) cn = vcol[nb];
            if (++spins > 4) __nanosleep(32);
        }

        unsigned lo = 0u, hi = 0u;
        if (need) {
            if (cn < 32) lo = 1u << cn; else hi = 1u << (cn - 32);
        }
        lo = __reduce_or_sync(FULL, lo);
        hi = __reduce_or_sync(FULL, hi);

        bool m0 = (lo >> lane) & 1u;
        bool m1 = (!ok1) || ((hi >> lane) & 1u);
        float s0 = m0 ? NEGINF : (l0 + g0);
        float s1 = m1 ? NEGINF : (l1 + g1);
        float s; int idx;
        if (s1 > s0) { s = s1; idx = c1; } else { s = s0; idx = lane; }
        unsigned e = fenc(s);
        unsigned m = __reduce_max_sync(FULL, e);
        unsigned ic = (e == m) ? (unsigned)idx : 64u;
        int chosen = (int)__reduce_min_sync(FULL, ic);

        if (lane == 0) vcol[v] = chosen;   // publish ASAP (critical path)

        // ---- logp term (off critical path) ----
        float mx = fmaxf(m0 ? NEGINF : l0, m1 ? NEGINF : l1);
        mx = fdec(__reduce_max_sync(FULL, fenc(mx)));
        float ex = (m0 ? 0.f : expf(l0 - mx)) + (m1 ? 0.f : expf(l1 - mx));
#pragma unroll
        for (int o = 16; o; o >>= 1) ex += __shfl_xor_sync(FULL, ex, o);
        float la = __shfl_sync(FULL, l0, chosen & 31);
        float lb = __shfl_sync(FULL, l1, chosen & 31);
        if (lane == 0) {
            float lc = (chosen < 32) ? la : lb;
            float prob = expf(lc - mx) / ex;
            g_terms[t] = logf(prob + 1e-8f) + 18.420680743952367f;
        }
    }
}

// ---------------- violation count ----------------
__global__ void viol_kernel(const int* __restrict__ adj)
{
    int i = blockIdx.x * blockDim.x + threadIdx.x;
    int c = 0;
    if (i < NV * DV) {
        int n = i >> 5;            // DV == 32
        c = (g_colors[adj[i]] == g_colors[n]) ? 1 : 0;
    }
    c = __reduce_add_sync(0xffffffffu, c);
    if ((threadIdx.x & 31) == 0 && c) atomicAdd(&g_viol, c);
}

// ---------------- output ----------------
__global__ void colors_out_kernel(float* out)
{
    int i = blockIdx.x * blockDim.x + threadIdx.x;
    if (i < NV) out[i] = (float)g_colors[i];
}

__global__ void final_kernel(float* out, int mode)
{
    const int tid = threadIdx.x;
    float s = 0.f;
    for (int t = 1 + tid; t < NV; t += 1024) s += g_terms[t];
    unsigned long long um = 0ull;
    for (int i = tid; i < NV; i += 1024) um |= (1ull << (g_colors[i] & 63));
#pragma unroll
    for (int o = 16; o; o >>= 1) {
        s  += __shfl_xor_sync(0xffffffffu, s, o);
        um |= __shfl_xor_sync(0xffffffffu, um, o);
    }
    __shared__ float ws[32];
    __shared__ unsigned long long wm[32];
    int w = tid >> 5, l = tid & 31;
    if (l == 0) { ws[w] = s; wm[w] = um; }
    __syncthreads();
    if (tid == 0) {
        float tot = 0.f; unsigned long long m = 0ull;
        for (int i = 0; i < 32; i++) { tot += ws[i]; m |= wm[i]; }
        float confidence = tot / (float)NV;
        int nused = __popcll(m);
        float ratio = (float)g_viol / (float)(NV * DV);
        float cost = (float)nused + ratio * 100.0f;
        float loss = cost * confidence;
        if (mode == 0) out[NV] = loss;
        else           out[0]  = loss;
    }
}

// ---------------- host ----------------
extern "C" void kernel_launch(void* const* d_in, const int* in_sizes, int n_in,
                              void* d_out, int out_size)
{
    const float *emb = 0, *W1 = 0, *b1 = 0, *W2 = 0, *b2 = 0,
                *W3 = 0, *b3 = 0, *W4 = 0, *b4 = 0;
    const int *adj = 0, *vorder = 0;
    for (int i = 0; i < n_in; i++) {
        long s = in_sizes[i];
        void* p = d_in[i];
        if      (s == (long)NV * EV)  emb = (const float*)p;
        else if (s == (long)NV * DV)  adj = (const int*)p;
        else if (s == NV)             vorder = (const int*)p;
        else if (s == (long)EV * EV)  { if (!W1) W1 = (const float*)p; else W2 = (const float*)p; }
        else if (s == EV)             { if (!b1) b1 = (const float*)p; else b2 = (const float*)p; }
        else if (s == (long)EV * H3V) W3 = (const float*)p;
        else if (s == H3V)            b3 = (const float*)p;
        else if (s == (long)H3V * CV) W4 = (const float*)p;
        else if (s == CV)             b4 = (const float*)p;
    }
    if (!emb || !adj || !vorder || !W1 || !b1 || !W2 || !b2 || !W3 || !b3 || !W4 || !b4)
        return;

    float *h1, *h2, *logits;
    cudaGetSymbolAddress((void**)&h1, g_bufA);
    cudaGetSymbolAddress((void**)&h2, g_bufB);
    cudaGetSymbolAddress((void**)&logits, g_logits);

    dim3 blk(256);
    gemm_kernel<128,64,16,8,4><<<dim3(EV / 64, NV / 128), blk>>>(
        emb, W1, b1, h1, NV, EV, EV, EV, EV, 1);
    gemm_kernel<128,64,16,8,4><<<dim3(EV / 64, NV / 128), blk>>>(
        h1, W2, b2, h2, NV, EV, EV, EV, EV, 1);
    gemm_kernel<128,64,16,8,4><<<dim3((H3V + 63) / 64, NV / 128), blk>>>(
        h2, W3, b3, h1, NV, EV, H3V, EV, H3V, 1);
    gemm_kernel<128,64,16,8,4><<<dim3(1, NV / 128), blk>>>(
        h1, W4, b4, logits, NV, H3V, CV, H3V, CV, 0);

    gumbel_kernel<<<((NV - 1) * CV + 255) / 256, 256>>>();
    pos_kernel<<<(NV + 255) / 256, 256>>>(vorder);

    wavescan_kernel<<<SCAN_BLOCKS, SCAN_TPB>>>(vorder, adj);

    viol_kernel<<<(NV * DV + 255) / 256, 256>>>(adj);

    float* outF = (float*)d_out;
    if (out_size >= NV)
        colors_out_kernel<<<(NV + 255) / 256, 256>>>(outF);
    int mode = (out_size >= NV + 1) ? 0 : ((out_size < NV) ? 1 : 2);
    if (mode != 2)
        final_kernel<<<1, 1024>>>(outF, mode);
}

// round 6
// speedup vs baseline: 6.9754x; 1.5137x over previous
#include <cuda_runtime.h>
#include <math.h>
#include <stdint.h>

#define NV 32768
#define EV 512
#define DV 32
#define CV 50
#define H3V 281
#define H3P 384          // padded fc3 width
#define LDL 128          // padded logits width
#define FULLM 0xffffffffu

// ---------------- device scratch (static, no allocation) ----------------
__device__ float g_bufA[NV * EV];
__device__ float g_bufB[NV * EV];
__device__ float g_logits[NV * LDL];
__device__ float g_gumbel[NV * CV];
__device__ float g_terms[NV];
__device__ int   g_colors[NV];
__device__ int   g_pos[NV];
__device__ int   g_viol;
__device__ int   g_next;
// transposed + tf32-split + padded weights: [Np][Kp]
__device__ float g_W1h[EV * EV],  g_W1l[EV * EV];
__device__ float g_W2h[EV * EV],  g_W2l[EV * EV];
__device__ float g_W3h[H3P * EV], g_W3l[H3P * EV];
__device__ float g_W4h[LDL * H3P], g_W4l[LDL * H3P];
__device__ float g_b3p[H3P];
__device__ float g_b4p[LDL];

// ---------------- helpers ----------------
__device__ __forceinline__ unsigned fenc(float f) {
    unsigned u = __float_as_uint(f);
    return (u & 0x80000000u) ? ~u : (u | 0x80000000u);
}
__device__ __forceinline__ float fdec(unsigned u) {
    return (u & 0x80000000u) ? __uint_as_float(u ^ 0x80000000u)
                             : __uint_as_float(~u);
}
__device__ __forceinline__ unsigned rotl32(unsigned x, int r) {
    return (x << r) | (x >> (32 - r));
}
__device__ __forceinline__ float tf32_rn(float a) {
    unsigned r;
    asm("cvt.rna.tf32.f32 %0, %1;" : "=r"(r) : "f"(a));
    return __uint_as_float(r);
}

#define MMA_TF32(d, a, b) \
    asm volatile("mma.sync.aligned.m16n8k8.row.col.f32.tf32.tf32.f32 " \
        "{%0,%1,%2,%3}, {%4,%5,%6,%7}, {%8,%9}, {%0,%1,%2,%3};" \
        : "+f"((d)[0]), "+f"((d)[1]), "+f"((d)[2]), "+f"((d)[3]) \
        : "r"((a)[0]), "r"((a)[1]), "r"((a)[2]), "r"((a)[3]), \
          "r"((b)[0]), "r"((b)[1]))

// ---------------- weight prep: transpose + tf32-split + pad --------------
__global__ void prep_w_kernel(const float* __restrict__ W, float* __restrict__ Wh,
                              float* __restrict__ Wl, int K, int N, int Kp, int Np)
{
    int idx = blockIdx.x * blockDim.x + threadIdx.x;
    if (idx >= Np * Kp) return;
    int n = idx / Kp, k = idx % Kp;
    float w = (n < N && k < K) ? W[(size_t)k * N + n] : 0.f;
    float hi = tf32_rn(w);
    float lo = tf32_rn(w - hi);
    Wh[idx] = hi;
    Wl[idx] = lo;
}
__global__ void prep_b_kernel(const float* __restrict__ b, float* __restrict__ bp,
                              int N, int Np)
{
    int i = blockIdx.x * blockDim.x + threadIdx.x;
    if (i < Np) bp[i] = (i < N) ? b[i] : 0.f;
}

// ---------------- 3xTF32 mma.sync GEMM: C = act(A @ Wt^T + bias) ---------
// A [M, Kp] fp32 row-major; Bh/Bl [Np, Kp] pre-split tf32; tile 128x128.
// 8 warps: warp (wm = wid&1, wn = wid>>1) computes 64x32 via m16n8k8 frags.
// smem stride 36 floats => conflict-free fragment loads.
#define GSTRIDE 36
#define GA_H 0
#define GA_L (128 * GSTRIDE)
#define GB_H (2 * 128 * GSTRIDE)
#define GB_L (3 * 128 * GSTRIDE)
#define GT_SMEM (4 * 128 * GSTRIDE * 4)   // 73728 bytes

__global__ void __launch_bounds__(256) gemm_tc_kernel(
    const float* __restrict__ A, const float* __restrict__ Bh,
    const float* __restrict__ Bl, const float* __restrict__ bias,
    float* __restrict__ C, int Kp, int Np, int lda, int ldc, int act)
{
    extern __shared__ float sm[];
    const int tid  = threadIdx.x;
    const int wid  = tid >> 5;
    const int lane = tid & 31;
    const int lr   = lane >> 2;       // 0..7
    const int lc   = lane & 3;        // 0..3
    const int wm   = wid & 1;         // 0..1  (row half)
    const int wn   = wid >> 1;        // 0..3  (col quarter)
    const int rowBase = blockIdx.y * 128;
    const int colBase = blockIdx.x * 128;

    float acc[4][4][4];
#pragma unroll
    for (int mt = 0; mt < 4; mt++)
#pragma unroll
        for (int nt = 0; nt < 4; nt++)
#pragma unroll
            for (int q = 0; q < 4; q++) acc[mt][nt][q] = 0.f;

    const int nchunks = Kp / 32;
    for (int ch = 0; ch < nchunks; ch++) {
        const int kb = ch * 32;
        if (ch) __syncthreads();
        // stage A (fp32 -> hi/lo) and pre-split B: 128 rows x 32 floats each
#pragma unroll
        for (int i = 0; i < 4; i++) {
            int idx = tid + 256 * i;          // 0..1023
            int r = idx >> 3, q = idx & 7;
            float4 av = *(const float4*)(A + (size_t)(rowBase + r) * lda + kb + 4 * q);
            float4 hi, lo;
            hi.x = tf32_rn(av.x); lo.x = tf32_rn(av.x - hi.x);
            hi.y = tf32_rn(av.y); lo.y = tf32_rn(av.y - hi.y);
            hi.z = tf32_rn(av.z); lo.z = tf32_rn(av.z - hi.z);
            hi.w = tf32_rn(av.w); lo.w = tf32_rn(av.w - hi.w);
            int so = r * GSTRIDE + 4 * q;
            *(float4*)(sm + GA_H + so) = hi;
            *(float4*)(sm + GA_L + so) = lo;
            *(float4*)(sm + GB_H + so) =
                *(const float4*)(Bh + (size_t)(colBase + r) * Kp + kb + 4 * q);
            *(float4*)(sm + GB_L + so) =
                *(const float4*)(Bl + (size_t)(colBase + r) * Kp + kb + 4 * q);
        }
        __syncthreads();

#pragma unroll
        for (int ks = 0; ks < 4; ks++) {
            const int k0 = ks * 8;
            unsigned aH[4][4], aL[4][4], bH[4][2], bL[4][2];
#pragma unroll
            for (int mt = 0; mt < 4; mt++) {
                int base = (wm * 64 + mt * 16 + lr) * GSTRIDE + k0 + lc;
                aH[mt][0] = __float_as_uint(sm[GA_H + base]);
                aH[mt][1] = __float_as_uint(sm[GA_H + base + 8 * GSTRIDE]);
                aH[mt][2] = __float_as_uint(sm[GA_H + base + 4]);
                aH[mt][3] = __float_as_uint(sm[GA_H + base + 8 * GSTRIDE + 4]);
                aL[mt][0] = __float_as_uint(sm[GA_L + base]);
                aL[mt][1] = __float_as_uint(sm[GA_L + base + 8 * GSTRIDE]);
                aL[mt][2] = __float_as_uint(sm[GA_L + base + 4]);
                aL[mt][3] = __float_as_uint(sm[GA_L + base + 8 * GSTRIDE + 4]);
            }
#pragma unroll
            for (int nt = 0; nt < 4; nt++) {
                int base = (wn * 32 + nt * 8 + lr) * GSTRIDE + k0 + lc;
                bH[nt][0] = __float_as_uint(sm[GB_H + base]);
                bH[nt][1] = __float_as_uint(sm[GB_H + base + 4]);
                bL[nt][0] = __float_as_uint(sm[GB_L + base]);
                bL[nt][1] = __float_as_uint(sm[GB_L + base + 4]);
            }
#pragma unroll
            for (int mt = 0; mt < 4; mt++)
#pragma unroll
                for (int nt = 0; nt < 4; nt++) {
                    MMA_TF32(acc[mt][nt], aL[mt], bH[nt]);
                    MMA_TF32(acc[mt][nt], aH[mt], bL[nt]);
                    MMA_TF32(acc[mt][nt], aH[mt], bH[nt]);
                }
        }
    }

    // epilogue: bias + leaky + store
#pragma unroll
    for (int mt = 0; mt < 4; mt++) {
        int row = rowBase + wm * 64 + mt * 16 + lr;
#pragma unroll
        for (int nt = 0; nt < 4; nt++) {
            int col = colBase + wn * 32 + nt * 8 + lc * 2;
            float v0 = acc[mt][nt][0] + bias[col];
            float v1 = acc[mt][nt][1] + bias[col + 1];
            float v2 = acc[mt][nt][2] + bias[col];
            float v3 = acc[mt][nt][3] + bias[col + 1];
            if (act) {
                v0 = (v0 >= 0.f) ? v0 : 0.01f * v0;
                v1 = (v1 >= 0.f) ? v1 : 0.01f * v1;
                v2 = (v2 >= 0.f) ? v2 : 0.01f * v2;
                v3 = (v3 >= 0.f) ? v3 : 0.01f * v3;
            }
            C[(size_t)row * ldc + col]           = v0;
            C[(size_t)row * ldc + col + 1]       = v1;
            C[(size_t)(row + 8) * ldc + col]     = v2;
            C[(size_t)(row + 8) * ldc + col + 1] = v3;
        }
    }
}

// ---------------- gumbel via PARTITIONABLE Threefry-2x32 (UNCHANGED) -----
__global__ void gumbel_kernel()
{
    const int total = (NV - 1) * CV;
    int i = blockIdx.x * blockDim.x + threadIdx.x;
    if (i >= total) return;
    unsigned x0 = 0u;
    unsigned x1 = (unsigned)i;
    const unsigned k0 = 0u, k1 = 42u, k2 = 0u ^ 42u ^ 0x1BD11BDAu;
    x0 += k0; x1 += k1;
#define TFR(r) { x0 += x1; x1 = rotl32(x1, r); x1 ^= x0; }
    TFR(13) TFR(15) TFR(26) TFR(6)  x0 += k1; x1 += k2 + 1u;
    TFR(17) TFR(29) TFR(16) TFR(24) x0 += k2; x1 += k0 + 2u;
    TFR(13) TFR(15) TFR(26) TFR(6)  x0 += k0; x1 += k1 + 3u;
    TFR(17) TFR(29) TFR(16) TFR(24) x0 += k1; x1 += k2 + 4u;
    TFR(13) TFR(15) TFR(26) TFR(6)  x0 += k2; x1 += k0 + 5u;
#undef TFR
    unsigned bits = x0 ^ x1;
    unsigned fb = (bits >> 9) | 0x3f800000u;
    float f = __uint_as_float(fb) - 1.0f;
    const float tiny = 1.17549435e-38f;
    float u = fmaxf(tiny, f + tiny);
    g_gumbel[i] = -logf(-logf(u));
}

// ---------------- pos scatter + colors init + counters -------------------
__global__ void pos_kernel(const int* __restrict__ vorder)
{
    int i = blockIdx.x * blockDim.x + threadIdx.x;
    if (i < NV) {
        g_pos[vorder[i]] = i;
        g_colors[i] = -1;
    }
    if (i == 0) { g_viol = 0; g_next = 1; }
}

// ---------------- wavefront dataflow scan (dynamic assignment) -----------
#define SCAN_BLOCKS 148
#define SCAN_TPB    256

__global__ void __launch_bounds__(SCAN_TPB) wavescan_kernel(
    const int* __restrict__ vorder, const int* __restrict__ adj)
{
    const int lane = threadIdx.x & 31;
    volatile int* vcol = g_colors;

    if (blockIdx.x == 0 && threadIdx.x == 0) {
        vcol[vorder[0]] = 0;               // first vertex -> color 0
    }

    const int c1 = lane + 32;
    const bool ok1 = (c1 < CV);
    const float NEGINF = __int_as_float((int)0xff800000);

    for (;;) {
        int t;
        if (lane == 0) t = atomicAdd(&g_next, 1);
        t = __shfl_sync(FULLM, t, 0);
        if (t >= NV) break;

        int v  = vorder[t];
        int nb = adj[v * DV + lane];
        int pn = g_pos[nb];
        float l0 = g_logits[v * LDL + lane];
        float l1 = ok1 ? g_logits[v * LDL + c1] : 0.f;
        float g0 = g_gumbel[(t - 1) * CV + lane];
        float g1 = ok1 ? g_gumbel[(t - 1) * CV + c1] : 0.f;

        bool need = (pn < t);
        int cn = -1;
        while (__any_sync(FULLM, need && cn < 0)) {
            if (need && cn < 0) cn = vcol[nb];
        }

        unsigned lo = 0u, hi = 0u;
        if (need) {
            if (cn < 32) lo = 1u << cn; else hi = 1u << (cn - 32);
        }
        lo = __reduce_or_sync(FULLM, lo);
        hi = __reduce_or_sync(FULLM, hi);

        bool m0 = (lo >> lane) & 1u;
        bool m1 = (!ok1) || ((hi >> lane) & 1u);
        float s0 = m0 ? NEGINF : (l0 + g0);
        float s1 = m1 ? NEGINF : (l1 + g1);
        float s; int idx;
        if (s1 > s0) { s = s1; idx = c1; } else { s = s0; idx = lane; }
        unsigned e = fenc(s);
        unsigned m = __reduce_max_sync(FULLM, e);
        unsigned ic = (e == m) ? (unsigned)idx : 64u;
        int chosen = (int)__reduce_min_sync(FULLM, ic);

        if (lane == 0) vcol[v] = chosen;   // publish ASAP

        // ---- logp term (off critical path) ----
        float mx = fmaxf(m0 ? NEGINF : l0, m1 ? NEGINF : l1);
        mx = fdec(__reduce_max_sync(FULLM, fenc(mx)));
        float ex = (m0 ? 0.f : expf(l0 - mx)) + (m1 ? 0.f : expf(l1 - mx));
#pragma unroll
        for (int o = 16; o; o >>= 1) ex += __shfl_xor_sync(FULLM, ex, o);
        float la = __shfl_sync(FULLM, l0, chosen & 31);
        float lb = __shfl_sync(FULLM, l1, chosen & 31);
        if (lane == 0) {
            float lc = (chosen < 32) ? la : lb;
            float prob = expf(lc - mx) / ex;
            g_terms[t] = logf(prob + 1e-8f) + 18.420680743952367f;
        }
    }
}

// ---------------- violation count ----------------
__global__ void viol_kernel(const int* __restrict__ adj)
{
    int i = blockIdx.x * blockDim.x + threadIdx.x;
    int c = 0;
    if (i < NV * DV) {
        int n = i >> 5;            // DV == 32
        c = (g_colors[adj[i]] == g_colors[n]) ? 1 : 0;
    }
    c = __reduce_add_sync(FULLM, c);
    if ((threadIdx.x & 31) == 0 && c) atomicAdd(&g_viol, c);
}

// ---------------- output ----------------
__global__ void colors_out_kernel(float* out)
{
    int i = blockIdx.x * blockDim.x + threadIdx.x;
    if (i < NV) out[i] = (float)g_colors[i];
}

__global__ void final_kernel(float* out, int mode)
{
    const int tid = threadIdx.x;
    float s = 0.f;
    for (int t = 1 + tid; t < NV; t += 1024) s += g_terms[t];
    unsigned long long um = 0ull;
    for (int i = tid; i < NV; i += 1024) um |= (1ull << (g_colors[i] & 63));
#pragma unroll
    for (int o = 16; o; o >>= 1) {
        s  += __shfl_xor_sync(FULLM, s, o);
        um |= __shfl_xor_sync(FULLM, um, o);
    }
    __shared__ float ws[32];
    __shared__ unsigned long long wm[32];
    int w = tid >> 5, l = tid & 31;
    if (l == 0) { ws[w] = s; wm[w] = um; }
    __syncthreads();
    if (tid == 0) {
        float tot = 0.f; unsigned long long m = 0ull;
        for (int i = 0; i < 32; i++) { tot += ws[i]; m |= wm[i]; }
        float confidence = tot / (float)NV;
        int nused = __popcll(m);
        float ratio = (float)g_viol / (float)(NV * DV);
        float cost = (float)nused + ratio * 100.0f;
        float loss = cost * confidence;
        if (mode == 0) out[NV] = loss;
        else           out[0]  = loss;
    }
}

// ---------------- host ----------------
extern "C" void kernel_launch(void* const* d_in, const int* in_sizes, int n_in,
                              void* d_out, int out_size)
{
    const float *emb = 0, *W1 = 0, *b1 = 0, *W2 = 0, *b2 = 0,
                *W3 = 0, *b3 = 0, *W4 = 0, *b4 = 0;
    const int *adj = 0, *vorder = 0;
    for (int i = 0; i < n_in; i++) {
        long s = in_sizes[i];
        void* p = d_in[i];
        if      (s == (long)NV * EV)  emb = (const float*)p;
        else if (s == (long)NV * DV)  adj = (const int*)p;
        else if (s == NV)             vorder = (const int*)p;
        else if (s == (long)EV * EV)  { if (!W1) W1 = (const float*)p; else W2 = (const float*)p; }
        else if (s == EV)             { if (!b1) b1 = (const float*)p; else b2 = (const float*)p; }
        else if (s == (long)EV * H3V) W3 = (const float*)p;
        else if (s == H3V)            b3 = (const float*)p;
        else if (s == (long)H3V * CV) W4 = (const float*)p;
        else if (s == CV)             b4 = (const float*)p;
    }
    if (!emb || !adj || !vorder || !W1 || !b1 || !W2 || !b2 || !W3 || !b3 || !W4 || !b4)
        return;

    float *h1, *h2, *logits;
    float *w1h, *w1l, *w2h, *w2l, *w3h, *w3l, *w4h, *w4l, *b3p, *b4p;
    cudaGetSymbolAddress((void**)&h1, g_bufA);
    cudaGetSymbolAddress((void**)&h2, g_bufB);
    cudaGetSymbolAddress((void**)&logits, g_logits);
    cudaGetSymbolAddress((void**)&w1h, g_W1h); cudaGetSymbolAddress((void**)&w1l, g_W1l);
    cudaGetSymbolAddress((void**)&w2h, g_W2h); cudaGetSymbolAddress((void**)&w2l, g_W2l);
    cudaGetSymbolAddress((void**)&w3h, g_W3h); cudaGetSymbolAddress((void**)&w3l, g_W3l);
    cudaGetSymbolAddress((void**)&w4h, g_W4h); cudaGetSymbolAddress((void**)&w4l, g_W4l);
    cudaGetSymbolAddress((void**)&b3p, g_b3p); cudaGetSymbolAddress((void**)&b4p, g_b4p);

    cudaFuncSetAttribute(gemm_tc_kernel,
                         cudaFuncAttributeMaxDynamicSharedMemorySize, GT_SMEM);

    // weight prep (transpose + tf32 split + pad)
    prep_w_kernel<<<(EV * EV + 255) / 256, 256>>>(W1, w1h, w1l, EV, EV, EV, EV);
    prep_w_kernel<<<(EV * EV + 255) / 256, 256>>>(W2, w2h, w2l, EV, EV, EV, EV);
    prep_w_kernel<<<(H3P * EV + 255) / 256, 256>>>(W3, w3h, w3l, EV, H3V, EV, H3P);
    prep_w_kernel<<<(LDL * H3P + 255) / 256, 256>>>(W4, w4h, w4l, H3V, CV, H3P, LDL);
    prep_b_kernel<<<1, H3P>>>(b3, b3p, H3V, H3P);
    prep_b_kernel<<<1, LDL>>>(b4, b4p, CV, LDL);

    // MLP via 3xTF32 mma.sync GEMMs
    gemm_tc_kernel<<<dim3(EV / 128, NV / 128), 256, GT_SMEM>>>(
        emb, w1h, w1l, b1, h1, EV, EV, EV, EV, 1);
    gemm_tc_kernel<<<dim3(EV / 128, NV / 128), 256, GT_SMEM>>>(
        h1, w2h, w2l, b2, h2, EV, EV, EV, EV, 1);
    gemm_tc_kernel<<<dim3(H3P / 128, NV / 128), 256, GT_SMEM>>>(
        h2, w3h, w3l, b3p, h1, EV, H3P, EV, H3P, 1);
    gemm_tc_kernel<<<dim3(LDL / 128, NV / 128), 256, GT_SMEM>>>(
        h1, w4h, w4l, b4p, logits, H3P, LDL, H3P, LDL, 0);

    gumbel_kernel<<<((NV - 1) * CV + 255) / 256, 256>>>();
    pos_kernel<<<(NV + 255) / 256, 256>>>(vorder);

    wavescan_kernel<<<SCAN_BLOCKS, SCAN_TPB>>>(vorder, adj);

    viol_kernel<<<(NV * DV + 255) / 256, 256>>>(adj);

    float* outF = (float*)d_out;
    if (out_size >= NV)
        colors_out_kernel<<<(NV + 255) / 256, 256>>>(outF);
    int mode = (out_size >= NV + 1) ? 0 : ((out_size < NV) ? 1 : 2);
    if (mode != 2)
        final_kernel<<<1, 1024>>>(outF, mode);
}

// round 7
// speedup vs baseline: 9.2626x; 1.3279x over previous
#include <cuda_runtime.h>
#include <math.h>
#include <stdint.h>

#define NV 32768
#define EV 512
#define DV 32
#define CV 50
#define H3V 281
#define H3P 384          // padded fc3 width
#define LDL 128          // padded logits width
#define FULLM 0xffffffffu

// ---------------- device scratch (static, no allocation) ----------------
__device__ float g_bufA[NV * EV];
__device__ float g_bufB[NV * EV];
__device__ float g_logits[NV * LDL];
__device__ float g_gumbel[NV * CV];
__device__ float g_terms[NV];
__device__ int   g_colors[NV];
__device__ int   g_pos[NV];
__device__ int   g_viol;
__device__ int   g_next;
// transposed + tf32-split + padded weights: [Np][Kp]
__device__ float g_W1h[EV * EV],  g_W1l[EV * EV];
__device__ float g_W2h[EV * EV],  g_W2l[EV * EV];
__device__ float g_W3h[H3P * EV], g_W3l[H3P * EV];
__device__ float g_W4h[LDL * H3P], g_W4l[LDL * H3P];
__device__ float g_b3p[H3P];
__device__ float g_b4p[LDL];

// ---------------- helpers ----------------
__device__ __forceinline__ unsigned fenc(float f) {
    unsigned u = __float_as_uint(f);
    return (u & 0x80000000u) ? ~u : (u | 0x80000000u);
}
__device__ __forceinline__ float fdec(unsigned u) {
    return (u & 0x80000000u) ? __uint_as_float(u ^ 0x80000000u)
                             : __uint_as_float(~u);
}
__device__ __forceinline__ unsigned rotl32(unsigned x, int r) {
    return (x << r) | (x >> (32 - r));
}
__device__ __forceinline__ float tf32_rn(float a) {
    unsigned r;
    asm("cvt.rna.tf32.f32 %0, %1;" : "=r"(r) : "f"(a));
    return __uint_as_float(r);
}

#define MMA_TF32(d, a, b) \
    asm volatile("mma.sync.aligned.m16n8k8.row.col.f32.tf32.tf32.f32 " \
        "{%0,%1,%2,%3}, {%4,%5,%6,%7}, {%8,%9}, {%0,%1,%2,%3};" \
        : "+f"((d)[0]), "+f"((d)[1]), "+f"((d)[2]), "+f"((d)[3]) \
        : "r"((a)[0]), "r"((a)[1]), "r"((a)[2]), "r"((a)[3]), \
          "r"((b)[0]), "r"((b)[1]))

#define CPA16(dst, src) \
    asm volatile("cp.async.cg.shared.global [%0], [%1], 16;" \
                 :: "r"(dst), "l"(src) : "memory")
#define CP_COMMIT  asm volatile("cp.async.commit_group;" ::: "memory")
#define CP_WAIT(n) asm volatile("cp.async.wait_group %0;" :: "n"(n) : "memory")

// ---------------- weight prep: transpose + tf32-split + pad --------------
__global__ void prep_w_kernel(const float* __restrict__ W, float* __restrict__ Wh,
                              float* __restrict__ Wl, int K, int N, int Kp, int Np)
{
    int idx = blockIdx.x * blockDim.x + threadIdx.x;
    if (idx >= Np * Kp) return;
    int n = idx / Kp, k = idx % Kp;
    float w = (n < N && k < K) ? W[(size_t)k * N + n] : 0.f;
    float hi = tf32_rn(w);
    float lo = tf32_rn(w - hi);
    Wh[idx] = hi;
    Wl[idx] = lo;
}
__global__ void prep_b_kernel(const float* __restrict__ b, float* __restrict__ bp,
                              int N, int Np)
{
    int i = blockIdx.x * blockDim.x + threadIdx.x;
    if (i < Np) bp[i] = (i < N) ? b[i] : 0.f;
}

// ---------------- 3xTF32 mma.sync GEMM, cp.async double-buffered ---------
// A [M, Kp] fp32 row-major (raw); Bh/Bl [Np, Kp] pre-split tf32.
// Tile 128x128, K-chunk 32, 2-stage smem ring. A hi/lo split happens at
// fragment-load time in registers (bit-identical to staging-time split).
#define GSTRIDE 36
#define ARR_F   (128 * GSTRIDE)            // floats per array (4608)
#define STG_F   (3 * ARR_F)                // floats per stage
#define OFF_A   0
#define OFF_BH  ARR_F
#define OFF_BL  (2 * ARR_F)
#define GT_SMEM (2 * STG_F * 4)            // 110592 bytes

__global__ void __launch_bounds__(256) gemm_tc_kernel(
    const float* __restrict__ A, const float* __restrict__ Bh,
    const float* __restrict__ Bl, const float* __restrict__ bias,
    float* __restrict__ C, int Kp, int Np, int lda, int ldc, int act)
{
    extern __shared__ float sm[];
    const int tid  = threadIdx.x;
    const int wid  = tid >> 5;
    const int lane = tid & 31;
    const int lr   = lane >> 2;       // 0..7
    const int lc   = lane & 3;        // 0..3
    const int wm   = wid & 1;         // 0..1  (row half)
    const int wn   = wid >> 1;        // 0..3  (col quarter)
    const int rowBase = blockIdx.y * 128;
    const int colBase = blockIdx.x * 128;
    const uint32_t sbase = (uint32_t)__cvta_generic_to_shared(sm);

    // per-thread staging coords: thread covers 4 (row, q) pairs
    const int r0 = tid >> 3;          // 0..31 (+32 per i)
    const int q0 = tid & 7;           // 0..7

    float acc[4][4][4];
#pragma unroll
    for (int mt = 0; mt < 4; mt++)
#pragma unroll
        for (int nt = 0; nt < 4; nt++)
#pragma unroll
            for (int q = 0; q < 4; q++) acc[mt][nt][q] = 0.f;

    const int nchunks = Kp / 32;

#define STAGE(s, kb) do {                                                     \
        uint32_t sb_ = sbase + (s) * (STG_F * 4);                             \
        _Pragma("unroll")                                                     \
        for (int i_ = 0; i_ < 4; i_++) {                                      \
            int r_ = r0 + 32 * i_;                                            \
            uint32_t so_ = (uint32_t)((r_ * GSTRIDE + 4 * q0) * 4);           \
            CPA16(sb_ + OFF_A * 4 + so_,                                      \
                  A + (size_t)(rowBase + r_) * lda + (kb) + 4 * q0);          \
            CPA16(sb_ + OFF_BH * 4 + so_,                                     \
                  Bh + (size_t)(colBase + r_) * Kp + (kb) + 4 * q0);          \
            CPA16(sb_ + OFF_BL * 4 + so_,                                     \
                  Bl + (size_t)(colBase + r_) * Kp + (kb) + 4 * q0);          \
        }                                                                     \
        CP_COMMIT;                                                            \
    } while (0)

    STAGE(0, 0);

    for (int ch = 0; ch < nchunks; ch++) {
        if (ch + 1 < nchunks) {
            STAGE((ch + 1) & 1, (ch + 1) * 32);
            CP_WAIT(1);
        } else {
            CP_WAIT(0);
        }
        __syncthreads();

        const float* sA = sm + (ch & 1) * STG_F + OFF_A;
        const float* sBH = sm + (ch & 1) * STG_F + OFF_BH;
        const float* sBL = sm + (ch & 1) * STG_F + OFF_BL;

#pragma unroll
        for (int ks = 0; ks < 4; ks++) {
            const int k0 = ks * 8;
            unsigned aH[4][4], aL[4][4], bH[4][2], bL[4][2];
#pragma unroll
            for (int mt = 0; mt < 4; mt++) {
                int base = (wm * 64 + mt * 16 + lr) * GSTRIDE + k0 + lc;
                float r0v = sA[base];
                float r1v = sA[base + 8 * GSTRIDE];
                float r2v = sA[base + 4];
                float r3v = sA[base + 8 * GSTRIDE + 4];
                float h0 = tf32_rn(r0v), h1 = tf32_rn(r1v);
                float h2 = tf32_rn(r2v), h3 = tf32_rn(r3v);
                aH[mt][0] = __float_as_uint(h0);
                aH[mt][1] = __float_as_uint(h1);
                aH[mt][2] = __float_as_uint(h2);
                aH[mt][3] = __float_as_uint(h3);
                aL[mt][0] = __float_as_uint(tf32_rn(r0v - h0));
                aL[mt][1] = __float_as_uint(tf32_rn(r1v - h1));
                aL[mt][2] = __float_as_uint(tf32_rn(r2v - h2));
                aL[mt][3] = __float_as_uint(tf32_rn(r3v - h3));
            }
#pragma unroll
            for (int nt = 0; nt < 4; nt++) {
                int base = (wn * 32 + nt * 8 + lr) * GSTRIDE + k0 + lc;
                bH[nt][0] = __float_as_uint(sBH[base]);
                bH[nt][1] = __float_as_uint(sBH[base + 4]);
                bL[nt][0] = __float_as_uint(sBL[base]);
                bL[nt][1] = __float_as_uint(sBL[base + 4]);
            }
#pragma unroll
            for (int mt = 0; mt < 4; mt++)
#pragma unroll
                for (int nt = 0; nt < 4; nt++) {
                    MMA_TF32(acc[mt][nt], aL[mt], bH[nt]);
                    MMA_TF32(acc[mt][nt], aH[mt], bL[nt]);
                    MMA_TF32(acc[mt][nt], aH[mt], bH[nt]);
                }
        }
        __syncthreads();   // MMA(ch) done before stage ch+2 overwrites buffer
    }
#undef STAGE

    // epilogue: bias + leaky + store
#pragma unroll
    for (int mt = 0; mt < 4; mt++) {
        int row = rowBase + wm * 64 + mt * 16 + lr;
#pragma unroll
        for (int nt = 0; nt < 4; nt++) {
            int col = colBase + wn * 32 + nt * 8 + lc * 2;
            float v0 = acc[mt][nt][0] + bias[col];
            float v1 = acc[mt][nt][1] + bias[col + 1];
            float v2 = acc[mt][nt][2] + bias[col];
            float v3 = acc[mt][nt][3] + bias[col + 1];
            if (act) {
                v0 = (v0 >= 0.f) ? v0 : 0.01f * v0;
                v1 = (v1 >= 0.f) ? v1 : 0.01f * v1;
                v2 = (v2 >= 0.f) ? v2 : 0.01f * v2;
                v3 = (v3 >= 0.f) ? v3 : 0.01f * v3;
            }
            C[(size_t)row * ldc + col]           = v0;
            C[(size_t)row * ldc + col + 1]       = v1;
            C[(size_t)(row + 8) * ldc + col]     = v2;
            C[(size_t)(row + 8) * ldc + col + 1] = v3;
        }
    }
}

// ---------------- gumbel via PARTITIONABLE Threefry-2x32 (UNCHANGED) -----
__global__ void gumbel_kernel()
{
    const int total = (NV - 1) * CV;
    int i = blockIdx.x * blockDim.x + threadIdx.x;
    if (i >= total) return;
    unsigned x0 = 0u;
    unsigned x1 = (unsigned)i;
    const unsigned k0 = 0u, k1 = 42u, k2 = 0u ^ 42u ^ 0x1BD11BDAu;
    x0 += k0; x1 += k1;
#define TFR(r) { x0 += x1; x1 = rotl32(x1, r); x1 ^= x0; }
    TFR(13) TFR(15) TFR(26) TFR(6)  x0 += k1; x1 += k2 + 1u;
    TFR(17) TFR(29) TFR(16) TFR(24) x0 += k2; x1 += k0 + 2u;
    TFR(13) TFR(15) TFR(26) TFR(6)  x0 += k0; x1 += k1 + 3u;
    TFR(17) TFR(29) TFR(16) TFR(24) x0 += k1; x1 += k2 + 4u;
    TFR(13) TFR(15) TFR(26) TFR(6)  x0 += k2; x1 += k0 + 5u;
#undef TFR
    unsigned bits = x0 ^ x1;
    unsigned fb = (bits >> 9) | 0x3f800000u;
    float f = __uint_as_float(fb) - 1.0f;
    const float tiny = 1.17549435e-38f;
    float u = fmaxf(tiny, f + tiny);
    g_gumbel[i] = -logf(-logf(u));
}

// ---------------- pos scatter + colors init + counters -------------------
__global__ void pos_kernel(const int* __restrict__ vorder)
{
    int i = blockIdx.x * blockDim.x + threadIdx.x;
    if (i < NV) {
        g_pos[vorder[i]] = i;
        g_colors[i] = -1;
    }
    if (i == 0) { g_viol = 0; g_next = 1; }
}

// ---------------- wavefront dataflow scan (dynamic assignment) -----------
#define SCAN_BLOCKS 148
#define SCAN_TPB    256

__global__ void __launch_bounds__(SCAN_TPB) wavescan_kernel(
    const int* __restrict__ vorder, const int* __restrict__ adj)
{
    const int lane = threadIdx.x & 31;
    volatile int* vcol = g_colors;

    if (blockIdx.x == 0 && threadIdx.x == 0) {
        vcol[vorder[0]] = 0;               // first vertex -> color 0
    }

    const int c1 = lane + 32;
    const bool ok1 = (c1 < CV);
    const float NEGINF = __int_as_float((int)0xff800000);

    for (;;) {
        int t;
        if (lane == 0) t = atomicAdd(&g_next, 1);
        t = __shfl_sync(FULLM, t, 0);
        if (t >= NV) break;

        int v  = vorder[t];
        int nb = adj[v * DV + lane];
        int pn = g_pos[nb];
        float l0 = g_logits[v * LDL + lane];
        float l1 = ok1 ? g_logits[v * LDL + c1] : 0.f;
        float g0 = g_gumbel[(t - 1) * CV + lane];
        float g1 = ok1 ? g_gumbel[(t - 1) * CV + c1] : 0.f;

        bool need = (pn < t);
        int cn = -1;
        while (__any_sync(FULLM, need && cn < 0)) {
            if (need && cn < 0) cn = vcol[nb];
        }

        unsigned lo = 0u, hi = 0u;
        if (need) {
            if (cn < 32) lo = 1u << cn; else hi = 1u << (cn - 32);
        }
        lo = __reduce_or_sync(FULLM, lo);
        hi = __reduce_or_sync(FULLM, hi);

        bool m0 = (lo >> lane) & 1u;
        bool m1 = (!ok1) || ((hi >> lane) & 1u);
        float s0 = m0 ? NEGINF : (l0 + g0);
        float s1 = m1 ? NEGINF : (l1 + g1);
        float s; int idx;
        if (s1 > s0) { s = s1; idx = c1; } else { s = s0; idx = lane; }
        unsigned e = fenc(s);
        unsigned m = __reduce_max_sync(FULLM, e);
        unsigned ic = (e == m) ? (unsigned)idx : 64u;
        int chosen = (int)__reduce_min_sync(FULLM, ic);

        if (lane == 0) vcol[v] = chosen;   // publish ASAP

        // ---- logp term (off critical path) ----
        float mx = fmaxf(m0 ? NEGINF : l0, m1 ? NEGINF : l1);
        mx = fdec(__reduce_max_sync(FULLM, fenc(mx)));
        float ex = (m0 ? 0.f : expf(l0 - mx)) + (m1 ? 0.f : expf(l1 - mx));
#pragma unroll
        for (int o = 16; o; o >>= 1) ex += __shfl_xor_sync(FULLM, ex, o);
        float la = __shfl_sync(FULLM, l0, chosen & 31);
        float lb = __shfl_sync(FULLM, l1, chosen & 31);
        if (lane == 0) {
            float lc = (chosen < 32) ? la : lb;
            float prob = expf(lc - mx) / ex;
            g_terms[t] = logf(prob + 1e-8f) + 18.420680743952367f;
        }
    }
}

// ---------------- violation count ----------------
__global__ void viol_kernel(const int* __restrict__ adj)
{
    int i = blockIdx.x * blockDim.x + threadIdx.x;
    int c = 0;
    if (i < NV * DV) {
        int n = i >> 5;            // DV == 32
        c = (g_colors[adj[i]] == g_colors[n]) ? 1 : 0;
    }
    c = __reduce_add_sync(FULLM, c);
    if ((threadIdx.x & 31) == 0 && c) atomicAdd(&g_viol, c);
}

// ---------------- output ----------------
__global__ void colors_out_kernel(float* out)
{
    int i = blockIdx.x * blockDim.x + threadIdx.x;
    if (i < NV) out[i] = (float)g_colors[i];
}

__global__ void final_kernel(float* out, int mode)
{
    const int tid = threadIdx.x;
    float s = 0.f;
    for (int t = 1 + tid; t < NV; t += 1024) s += g_terms[t];
    unsigned long long um = 0ull;
    for (int i = tid; i < NV; i += 1024) um |= (1ull << (g_colors[i] & 63));
#pragma unroll
    for (int o = 16; o; o >>= 1) {
        s  += __shfl_xor_sync(FULLM, s, o);
        um |= __shfl_xor_sync(FULLM, um, o);
    }
    __shared__ float ws[32];
    __shared__ unsigned long long wm[32];
    int w = tid >> 5, l = tid & 31;
    if (l == 0) { ws[w] = s; wm[w] = um; }
    __syncthreads();
    if (tid == 0) {
        float tot = 0.f; unsigned long long m = 0ull;
        for (int i = 0; i < 32; i++) { tot += ws[i]; m |= wm[i]; }
        float confidence = tot / (float)NV;
        int nused = __popcll(m);
        float ratio = (float)g_viol / (float)(NV * DV);
        float cost = (float)nused + ratio * 100.0f;
        float loss = cost * confidence;
        if (mode == 0) out[NV] = loss;
        else           out[0]  = loss;
    }
}

// ---------------- host ----------------
extern "C" void kernel_launch(void* const* d_in, const int* in_sizes, int n_in,
                              void* d_out, int out_size)
{
    const float *emb = 0, *W1 = 0, *b1 = 0, *W2 = 0, *b2 = 0,
                *W3 = 0, *b3 = 0, *W4 = 0, *b4 = 0;
    const int *adj = 0, *vorder = 0;
    for (int i = 0; i < n_in; i++) {
        long s = in_sizes[i];
        void* p = d_in[i];
        if      (s == (long)NV * EV)  emb = (const float*)p;
        else if (s == (long)NV * DV)  adj = (const int*)p;
        else if (s == NV)             vorder = (const int*)p;
        else if (s == (long)EV * EV)  { if (!W1) W1 = (const float*)p; else W2 = (const float*)p; }
        else if (s == EV)             { if (!b1) b1 = (const float*)p; else b2 = (const float*)p; }
        else if (s == (long)EV * H3V) W3 = (const float*)p;
        else if (s == H3V)            b3 = (const float*)p;
        else if (s == (long)H3V * CV) W4 = (const float*)p;
        else if (s == CV)             b4 = (const float*)p;
    }
    if (!emb || !adj || !vorder || !W1 || !b1 || !W2 || !b2 || !W3 || !b3 || !W4 || !b4)
        return;

    float *h1, *h2, *logits;
    float *w1h, *w1l, *w2h, *w2l, *w3h, *w3l, *w4h, *w4l, *b3p, *b4p;
    cudaGetSymbolAddress((void**)&h1, g_bufA);
    cudaGetSymbolAddress((void**)&h2, g_bufB);
    cudaGetSymbolAddress((void**)&logits, g_logits);
    cudaGetSymbolAddress((void**)&w1h, g_W1h); cudaGetSymbolAddress((void**)&w1l, g_W1l);
    cudaGetSymbolAddress((void**)&w2h, g_W2h); cudaGetSymbolAddress((void**)&w2l, g_W2l);
    cudaGetSymbolAddress((void**)&w3h, g_W3h); cudaGetSymbolAddress((void**)&w3l, g_W3l);
    cudaGetSymbolAddress((void**)&w4h, g_W4h); cudaGetSymbolAddress((void**)&w4l, g_W4l);
    cudaGetSymbolAddress((void**)&b3p, g_b3p); cudaGetSymbolAddress((void**)&b4p, g_b4p);

    cudaFuncSetAttribute(gemm_tc_kernel,
                         cudaFuncAttributeMaxDynamicSharedMemorySize, GT_SMEM);

    // weight prep (transpose + tf32 split + pad)
    prep_w_kernel<<<(EV * EV + 255) / 256, 256>>>(W1, w1h, w1l, EV, EV, EV, EV);
    prep_w_kernel<<<(EV * EV + 255) / 256, 256>>>(W2, w2h, w2l, EV, EV, EV, EV);
    prep_w_kernel<<<(H3P * EV + 255) / 256, 256>>>(W3, w3h, w3l, EV, H3V, EV, H3P);
    prep_w_kernel<<<(LDL * H3P + 255) / 256, 256>>>(W4, w4h, w4l, H3V, CV, H3P, LDL);
    prep_b_kernel<<<1, H3P>>>(b3, b3p, H3V, H3P);
    prep_b_kernel<<<1, LDL>>>(b4, b4p, CV, LDL);

    // MLP via 3xTF32 mma.sync GEMMs (cp.async double-buffered)
    gemm_tc_kernel<<<dim3(EV / 128, NV / 128), 256, GT_SMEM>>>(
        emb, w1h, w1l, b1, h1, EV, EV, EV, EV, 1);
    gemm_tc_kernel<<<dim3(EV / 128, NV / 128), 256, GT_SMEM>>>(
        h1, w2h, w2l, b2, h2, EV, EV, EV, EV, 1);
    gemm_tc_kernel<<<dim3(H3P / 128, NV / 128), 256, GT_SMEM>>>(
        h2, w3h, w3l, b3p, h1, EV, H3P, EV, H3P, 1);
    gemm_tc_kernel<<<dim3(LDL / 128, NV / 128), 256, GT_SMEM>>>(
        h1, w4h, w4l, b4p, logits, H3P, LDL, H3P, LDL, 0);

    gumbel_kernel<<<((NV - 1) * CV + 255) / 256, 256>>>();
    pos_kernel<<<(NV + 255) / 256, 256>>>(vorder);

    wavescan_kernel<<<SCAN_BLOCKS, SCAN_TPB>>>(vorder, adj);

    viol_kernel<<<(NV * DV + 255) / 256, 256>>>(adj);

    float* outF = (float*)d_out;
    if (out_size >= NV)
        colors_out_kernel<<<(NV + 255) / 256, 256>>>(outF);
    int mode = (out_size >= NV + 1) ? 0 : ((out_size < NV) ? 1 : 2);
    if (mode != 2)
        final_kernel<<<1, 1024>>>(outF, mode);
}

// round 8
// speedup vs baseline: 9.5144x; 1.0272x over previous
#include <cuda_runtime.h>
#include <math.h>
#include <stdint.h>

#define NV 32768
#define EV 512
#define DV 32
#define CV 50
#define H3V 281
#define H3P 384          // padded fc3 width
#define LDL 128          // padded logits width
#define FULLM 0xffffffffu

// ---------------- device scratch (static, no allocation) ----------------
__device__ float g_bufA[NV * EV];
__device__ float g_bufB[NV * EV];
__device__ float g_logits[NV * LDL];
__device__ float g_gumbel[NV * CV];
__device__ float g_terms[NV];
__device__ int   g_colors[NV];
__device__ int   g_pos[NV];
__device__ int   g_viol;
__device__ int   g_next;
// transposed + tf32-split + padded weights: [Np][Kp]
__device__ float g_W1h[EV * EV],  g_W1l[EV * EV];
__device__ float g_W2h[EV * EV],  g_W2l[EV * EV];
__device__ float g_W3h[H3P * EV], g_W3l[H3P * EV];
__device__ float g_W4h[LDL * H3P], g_W4l[LDL * H3P];
__device__ float g_b3p[H3P];
__device__ float g_b4p[LDL];

// ---------------- helpers ----------------
__device__ __forceinline__ unsigned fenc(float f) {
    unsigned u = __float_as_uint(f);
    return (u & 0x80000000u) ? ~u : (u | 0x80000000u);
}
__device__ __forceinline__ float fdec(unsigned u) {
    return (u & 0x80000000u) ? __uint_as_float(u ^ 0x80000000u)
                             : __uint_as_float(~u);
}
__device__ __forceinline__ unsigned rotl32(unsigned x, int r) {
    return (x << r) | (x >> (32 - r));
}
__device__ __forceinline__ float tf32_rn(float a) {
    unsigned r;
    asm("cvt.rna.tf32.f32 %0, %1;" : "=r"(r) : "f"(a));
    return __uint_as_float(r);
}

#define MMA_TF32(d, a, b) \
    asm volatile("mma.sync.aligned.m16n8k8.row.col.f32.tf32.tf32.f32 " \
        "{%0,%1,%2,%3}, {%4,%5,%6,%7}, {%8,%9}, {%0,%1,%2,%3};" \
        : "+f"((d)[0]), "+f"((d)[1]), "+f"((d)[2]), "+f"((d)[3]) \
        : "r"((a)[0]), "r"((a)[1]), "r"((a)[2]), "r"((a)[3]), \
          "r"((b)[0]), "r"((b)[1]))

#define CPA16(dst, src) \
    asm volatile("cp.async.cg.shared.global [%0], [%1], 16;" \
                 :: "r"(dst), "l"(src) : "memory")
#define CP_COMMIT  asm volatile("cp.async.commit_group;" ::: "memory")
#define CP_WAIT(n) asm volatile("cp.async.wait_group %0;" :: "n"(n) : "memory")

// ---------------- fused weight prep (ONE launch) -------------------------
// Handles: W1,W2 (512x512), W3 (281x512 -> 384x512), W4 (281x50 -> 384x128),
// b3 pad, b4 pad. Transpose + tf32 hi/lo split + zero-pad.
#define PW1_END  (EV * EV)
#define PW2_END  (2 * EV * EV)
#define PW3_END  (2 * EV * EV + H3P * EV)
#define PW4_END  (2 * EV * EV + H3P * EV + LDL * H3P)
#define PB3_END  (PW4_END + H3P)
#define PB4_END  (PB3_END + LDL)

__global__ void prep_all_kernel(const float* __restrict__ W1,
                                const float* __restrict__ W2,
                                const float* __restrict__ W3,
                                const float* __restrict__ W4,
                                const float* __restrict__ b3,
                                const float* __restrict__ b4)
{
    int gi = blockIdx.x * blockDim.x + threadIdx.x;
    if (gi < PW2_END) {
        const float* W; float *Wh, *Wl; int idx;
        if (gi < PW1_END) { W = W1; Wh = g_W1h; Wl = g_W1l; idx = gi; }
        else              { W = W2; Wh = g_W2h; Wl = g_W2l; idx = gi - PW1_END; }
        int n = idx / EV, k = idx % EV;
        float w = W[(size_t)k * EV + n];
        float hi = tf32_rn(w);
        Wh[idx] = hi; Wl[idx] = tf32_rn(w - hi);
    } else if (gi < PW3_END) {
        int idx = gi - PW2_END;
        int n = idx / EV, k = idx % EV;
        float w = (n < H3V) ? W3[(size_t)k * H3V + n] : 0.f;
        float hi = tf32_rn(w);
        g_W3h[idx] = hi; g_W3l[idx] = tf32_rn(w - hi);
    } else if (gi < PW4_END) {
        int idx = gi - PW3_END;
        int n = idx / H3P, k = idx % H3P;
        float w = (n < CV && k < H3V) ? W4[(size_t)k * CV + n] : 0.f;
        float hi = tf32_rn(w);
        g_W4h[idx] = hi; g_W4l[idx] = tf32_rn(w - hi);
    } else if (gi < PB3_END) {
        int i = gi - PW4_END;
        g_b3p[i] = (i < H3V) ? b3[i] : 0.f;
    } else if (gi < PB4_END) {
        int i = gi - PB3_END;
        g_b4p[i] = (i < CV) ? b4[i] : 0.f;
    }
}

// ---------------- 3xTF32 mma.sync GEMM, cp.async double-buffered ---------
#define GSTRIDE 36
#define ARR_F   (128 * GSTRIDE)            // floats per array (4608)
#define STG_F   (3 * ARR_F)                // floats per stage
#define OFF_A   0
#define OFF_BH  ARR_F
#define OFF_BL  (2 * ARR_F)
#define GT_SMEM (2 * STG_F * 4)            // 110592 bytes

__global__ void __launch_bounds__(256) gemm_tc_kernel(
    const float* __restrict__ A, const float* __restrict__ Bh,
    const float* __restrict__ Bl, const float* __restrict__ bias,
    float* __restrict__ C, int Kp, int Np, int lda, int ldc, int act)
{
    extern __shared__ float sm[];
    const int tid  = threadIdx.x;
    const int wid  = tid >> 5;
    const int lane = tid & 31;
    const int lr   = lane >> 2;       // 0..7
    const int lc   = lane & 3;        // 0..3
    const int wm   = wid & 1;         // 0..1  (row half)
    const int wn   = wid >> 1;        // 0..3  (col quarter)
    const int rowBase = blockIdx.y * 128;
    const int colBase = blockIdx.x * 128;
    const uint32_t sbase = (uint32_t)__cvta_generic_to_shared(sm);

    const int r0 = tid >> 3;          // 0..31 (+32 per i)
    const int q0 = tid & 7;           // 0..7

    float acc[4][4][4];
#pragma unroll
    for (int mt = 0; mt < 4; mt++)
#pragma unroll
        for (int nt = 0; nt < 4; nt++)
#pragma unroll
            for (int q = 0; q < 4; q++) acc[mt][nt][q] = 0.f;

    const int nchunks = Kp / 32;

#define STAGE(s, kb) do {                                                     \
        uint32_t sb_ = sbase + (s) * (STG_F * 4);                             \
        _Pragma("unroll")                                                     \
        for (int i_ = 0; i_ < 4; i_++) {                                      \
            int r_ = r0 + 32 * i_;                                            \
            uint32_t so_ = (uint32_t)((r_ * GSTRIDE + 4 * q0) * 4);           \
            CPA16(sb_ + OFF_A * 4 + so_,                                      \
                  A + (size_t)(rowBase + r_) * lda + (kb) + 4 * q0);          \
            CPA16(sb_ + OFF_BH * 4 + so_,                                     \
                  Bh + (size_t)(colBase + r_) * Kp + (kb) + 4 * q0);          \
            CPA16(sb_ + OFF_BL * 4 + so_,                                     \
                  Bl + (size_t)(colBase + r_) * Kp + (kb) + 4 * q0);          \
        }                                                                     \
        CP_COMMIT;                                                            \
    } while (0)

    STAGE(0, 0);

    for (int ch = 0; ch < nchunks; ch++) {
        if (ch + 1 < nchunks) {
            STAGE((ch + 1) & 1, (ch + 1) * 32);
            CP_WAIT(1);
        } else {
            CP_WAIT(0);
        }
        __syncthreads();

        const float* sA  = sm + (ch & 1) * STG_F + OFF_A;
        const float* sBH = sm + (ch & 1) * STG_F + OFF_BH;
        const float* sBL = sm + (ch & 1) * STG_F + OFF_BL;

#pragma unroll
        for (int ks = 0; ks < 4; ks++) {
            const int k0 = ks * 8;
            unsigned aH[4][4], aL[4][4], bH[4][2], bL[4][2];
#pragma unroll
            for (int mt = 0; mt < 4; mt++) {
                int base = (wm * 64 + mt * 16 + lr) * GSTRIDE + k0 + lc;
                float r0v = sA[base];
                float r1v = sA[base + 8 * GSTRIDE];
                float r2v = sA[base + 4];
                float r3v = sA[base + 8 * GSTRIDE + 4];
                float h0 = tf32_rn(r0v), h1 = tf32_rn(r1v);
                float h2 = tf32_rn(r2v), h3 = tf32_rn(r3v);
                aH[mt][0] = __float_as_uint(h0);
                aH[mt][1] = __float_as_uint(h1);
                aH[mt][2] = __float_as_uint(h2);
                aH[mt][3] = __float_as_uint(h3);
                aL[mt][0] = __float_as_uint(tf32_rn(r0v - h0));
                aL[mt][1] = __float_as_uint(tf32_rn(r1v - h1));
                aL[mt][2] = __float_as_uint(tf32_rn(r2v - h2));
                aL[mt][3] = __float_as_uint(tf32_rn(r3v - h3));
            }
#pragma unroll
            for (int nt = 0; nt < 4; nt++) {
                int base = (wn * 32 + nt * 8 + lr) * GSTRIDE + k0 + lc;
                bH[nt][0] = __float_as_uint(sBH[base]);
                bH[nt][1] = __float_as_uint(sBH[base + 4]);
                bL[nt][0] = __float_as_uint(sBL[base]);
                bL[nt][1] = __float_as_uint(sBL[base + 4]);
            }
#pragma unroll
            for (int mt = 0; mt < 4; mt++)
#pragma unroll
                for (int nt = 0; nt < 4; nt++) {
                    MMA_TF32(acc[mt][nt], aL[mt], bH[nt]);
                    MMA_TF32(acc[mt][nt], aH[mt], bL[nt]);
                    MMA_TF32(acc[mt][nt], aH[mt], bH[nt]);
                }
        }
        __syncthreads();
    }
#undef STAGE

    // epilogue: bias + leaky + store
#pragma unroll
    for (int mt = 0; mt < 4; mt++) {
        int row = rowBase + wm * 64 + mt * 16 + lr;
#pragma unroll
        for (int nt = 0; nt < 4; nt++) {
            int col = colBase + wn * 32 + nt * 8 + lc * 2;
            float v0 = acc[mt][nt][0] + bias[col];
            float v1 = acc[mt][nt][1] + bias[col + 1];
            float v2 = acc[mt][nt][2] + bias[col];
            float v3 = acc[mt][nt][3] + bias[col + 1];
            if (act) {
                v0 = (v0 >= 0.f) ? v0 : 0.01f * v0;
                v1 = (v1 >= 0.f) ? v1 : 0.01f * v1;
                v2 = (v2 >= 0.f) ? v2 : 0.01f * v2;
                v3 = (v3 >= 0.f) ? v3 : 0.01f * v3;
            }
            C[(size_t)row * ldc + col]           = v0;
            C[(size_t)row * ldc + col + 1]       = v1;
            C[(size_t)(row + 8) * ldc + col]     = v2;
            C[(size_t)(row + 8) * ldc + col + 1] = v3;
        }
    }
}

// ---------------- gumbel via PARTITIONABLE Threefry-2x32 (UNCHANGED) -----
__global__ void gumbel_kernel()
{
    const int total = (NV - 1) * CV;
    int i = blockIdx.x * blockDim.x + threadIdx.x;
    if (i >= total) return;
    unsigned x0 = 0u;
    unsigned x1 = (unsigned)i;
    const unsigned k0 = 0u, k1 = 42u, k2 = 0u ^ 42u ^ 0x1BD11BDAu;
    x0 += k0; x1 += k1;
#define TFR(r) { x0 += x1; x1 = rotl32(x1, r); x1 ^= x0; }
    TFR(13) TFR(15) TFR(26) TFR(6)  x0 += k1; x1 += k2 + 1u;
    TFR(17) TFR(29) TFR(16) TFR(24) x0 += k2; x1 += k0 + 2u;
    TFR(13) TFR(15) TFR(26) TFR(6)  x0 += k0; x1 += k1 + 3u;
    TFR(17) TFR(29) TFR(16) TFR(24) x0 += k1; x1 += k2 + 4u;
    TFR(13) TFR(15) TFR(26) TFR(6)  x0 += k2; x1 += k0 + 5u;
#undef TFR
    unsigned bits = x0 ^ x1;
    unsigned fb = (bits >> 9) | 0x3f800000u;
    float f = __uint_as_float(fb) - 1.0f;
    const float tiny = 1.17549435e-38f;
    float u = fmaxf(tiny, f + tiny);
    g_gumbel[i] = -logf(-logf(u));
}

// ---------------- pos scatter + colors init + counters -------------------
__global__ void pos_kernel(const int* __restrict__ vorder)
{
    int i = blockIdx.x * blockDim.x + threadIdx.x;
    if (i < NV) {
        g_pos[vorder[i]] = i;
        g_colors[i] = -1;
    }
    if (i == 0) { g_viol = 0; g_next = 1; }
}

// ---------------- wavefront dataflow scan (dynamic assignment) -----------
// Widened: 148 x 512 = 2368 warps. Deadlock-free under any residency:
// counter order guarantees deps of any claimed step are already claimed.
#define SCAN_BLOCKS 148
#define SCAN_TPB    512

__global__ void __launch_bounds__(SCAN_TPB) wavescan_kernel(
    const int* __restrict__ vorder, const int* __restrict__ adj)
{
    const int lane = threadIdx.x & 31;
    volatile int* vcol = g_colors;

    if (blockIdx.x == 0 && threadIdx.x == 0) {
        vcol[vorder[0]] = 0;               // first vertex -> color 0
    }

    const int c1 = lane + 32;
    const bool ok1 = (c1 < CV);
    const float NEGINF = __int_as_float((int)0xff800000);

    for (;;) {
        int t;
        if (lane == 0) t = atomicAdd(&g_next, 1);
        t = __shfl_sync(FULLM, t, 0);
        if (t >= NV) break;

        int v  = vorder[t];
        int nb = adj[v * DV + lane];
        int pn = g_pos[nb];
        float l0 = g_logits[v * LDL + lane];
        float l1 = ok1 ? g_logits[v * LDL + c1] : 0.f;
        float g0 = g_gumbel[(t - 1) * CV + lane];
        float g1 = ok1 ? g_gumbel[(t - 1) * CV + c1] : 0.f;

        bool need = (pn < t);
        int cn = -1;
        while (__any_sync(FULLM, need && cn < 0)) {
            if (need && cn < 0) cn = vcol[nb];
        }

        unsigned lo = 0u, hi = 0u;
        if (need) {
            if (cn < 32) lo = 1u << cn; else hi = 1u << (cn - 32);
        }
        lo = __reduce_or_sync(FULLM, lo);
        hi = __reduce_or_sync(FULLM, hi);

        bool m0 = (lo >> lane) & 1u;
        bool m1 = (!ok1) || ((hi >> lane) & 1u);
        float s0 = m0 ? NEGINF : (l0 + g0);
        float s1 = m1 ? NEGINF : (l1 + g1);
        float s; int idx;
        if (s1 > s0) { s = s1; idx = c1; } else { s = s0; idx = lane; }
        unsigned e = fenc(s);
        unsigned m = __reduce_max_sync(FULLM, e);
        unsigned ic = (e == m) ? (unsigned)idx : 64u;
        int chosen = (int)__reduce_min_sync(FULLM, ic);

        if (lane == 0) vcol[v] = chosen;   // publish ASAP

        // ---- logp term (off critical path) ----
        float mx = fmaxf(m0 ? NEGINF : l0, m1 ? NEGINF : l1);
        mx = fdec(__reduce_max_sync(FULLM, fenc(mx)));
        float ex = (m0 ? 0.f : expf(l0 - mx)) + (m1 ? 0.f : expf(l1 - mx));
#pragma unroll
        for (int o = 16; o; o >>= 1) ex += __shfl_xor_sync(FULLM, ex, o);
        float la = __shfl_sync(FULLM, l0, chosen & 31);
        float lb = __shfl_sync(FULLM, l1, chosen & 31);
        if (lane == 0) {
            float lc = (chosen < 32) ? la : lb;
            float prob = expf(lc - mx) / ex;
            g_terms[t] = logf(prob + 1e-8f) + 18.420680743952367f;
        }
    }
}

// ---------------- violation count ----------------
__global__ void viol_kernel(const int* __restrict__ adj)
{
    int i = blockIdx.x * blockDim.x + threadIdx.x;
    int c = 0;
    if (i < NV * DV) {
        int n = i >> 5;            // DV == 32
        c = (g_colors[adj[i]] == g_colors[n]) ? 1 : 0;
    }
    c = __reduce_add_sync(FULLM, c);
    if ((threadIdx.x & 31) == 0 && c) atomicAdd(&g_viol, c);
}

// ---------------- output ----------------
__global__ void colors_out_kernel(float* out)
{
    int i = blockIdx.x * blockDim.x + threadIdx.x;
    if (i < NV) out[i] = (float)g_colors[i];
}

__global__ void final_kernel(float* out, int mode)
{
    const int tid = threadIdx.x;
    float s = 0.f;
    for (int t = 1 + tid; t < NV; t += 1024) s += g_terms[t];
    unsigned long long um = 0ull;
    for (int i = tid; i < NV; i += 1024) um |= (1ull << (g_colors[i] & 63));
#pragma unroll
    for (int o = 16; o; o >>= 1) {
        s  += __shfl_xor_sync(FULLM, s, o);
        um |= __shfl_xor_sync(FULLM, um, o);
    }
    __shared__ float ws[32];
    __shared__ unsigned long long wm[32];
    int w = tid >> 5, l = tid & 31;
    if (l == 0) { ws[w] = s; wm[w] = um; }
    __syncthreads();
    if (tid == 0) {
        float tot = 0.f; unsigned long long m = 0ull;
        for (int i = 0; i < 32; i++) { tot += ws[i]; m |= wm[i]; }
        float confidence = tot / (float)NV;
        int nused = __popcll(m);
        float ratio = (float)g_viol / (float)(NV * DV);
        float cost = (float)nused + ratio * 100.0f;
        float loss = cost * confidence;
        if (mode == 0) out[NV] = loss;
        else           out[0]  = loss;
    }
}

// ---------------- host ----------------
extern "C" void kernel_launch(void* const* d_in, const int* in_sizes, int n_in,
                              void* d_out, int out_size)
{
    const float *emb = 0, *W1 = 0, *b1 = 0, *W2 = 0, *b2 = 0,
                *W3 = 0, *b3 = 0, *W4 = 0, *b4 = 0;
    const int *adj = 0, *vorder = 0;
    for (int i = 0; i < n_in; i++) {
        long s = in_sizes[i];
        void* p = d_in[i];
        if      (s == (long)NV * EV)  emb = (const float*)p;
        else if (s == (long)NV * DV)  adj = (const int*)p;
        else if (s == NV)             vorder = (const int*)p;
        else if (s == (long)EV * EV)  { if (!W1) W1 = (const float*)p; else W2 = (const float*)p; }
        else if (s == EV)             { if (!b1) b1 = (const float*)p; else b2 = (const float*)p; }
        else if (s == (long)EV * H3V) W3 = (const float*)p;
        else if (s == H3V)            b3 = (const float*)p;
        else if (s == (long)H3V * CV) W4 = (const float*)p;
        else if (s == CV)             b4 = (const float*)p;
    }
    if (!emb || !adj || !vorder || !W1 || !b1 || !W2 || !b2 || !W3 || !b3 || !W4 || !b4)
        return;

    float *h1, *h2, *logits;
    float *w1h, *w1l, *w2h, *w2l, *w3h, *w3l, *w4h, *w4l, *b3p, *b4p;
    cudaGetSymbolAddress((void**)&h1, g_bufA);
    cudaGetSymbolAddress((void**)&h2, g_bufB);
    cudaGetSymbolAddress((void**)&logits, g_logits);
    cudaGetSymbolAddress((void**)&w1h, g_W1h); cudaGetSymbolAddress((void**)&w1l, g_W1l);
    cudaGetSymbolAddress((void**)&w2h, g_W2h); cudaGetSymbolAddress((void**)&w2l, g_W2l);
    cudaGetSymbolAddress((void**)&w3h, g_W3h); cudaGetSymbolAddress((void**)&w3l, g_W3l);
    cudaGetSymbolAddress((void**)&w4h, g_W4h); cudaGetSymbolAddress((void**)&w4l, g_W4l);
    cudaGetSymbolAddress((void**)&b3p, g_b3p); cudaGetSymbolAddress((void**)&b4p, g_b4p);

    cudaFuncSetAttribute(gemm_tc_kernel,
                         cudaFuncAttributeMaxDynamicSharedMemorySize, GT_SMEM);

    // fused weight prep (launch index 0)
    prep_all_kernel<<<(PB4_END + 255) / 256, 256>>>(W1, W2, W3, W4, b3, b4);

    // MLP GEMMs (launch indices 1..4 — index 3 = gemm3 gets profiled)
    gemm_tc_kernel<<<dim3(EV / 128, NV / 128), 256, GT_SMEM>>>(
        emb, w1h, w1l, b1, h1, EV, EV, EV, EV, 1);
    gemm_tc_kernel<<<dim3(EV / 128, NV / 128), 256, GT_SMEM>>>(
        h1, w2h, w2l, b2, h2, EV, EV, EV, EV, 1);
    gemm_tc_kernel<<<dim3(H3P / 128, NV / 128), 256, GT_SMEM>>>(
        h2, w3h, w3l, b3p, h1, EV, H3P, EV, H3P, 1);
    gemm_tc_kernel<<<dim3(LDL / 128, NV / 128), 256, GT_SMEM>>>(
        h1, w4h, w4l, b4p, logits, H3P, LDL, H3P, LDL, 0);

    gumbel_kernel<<<((NV - 1) * CV + 255) / 256, 256>>>();
    pos_kernel<<<(NV + 255) / 256, 256>>>(vorder);

    wavescan_kernel<<<SCAN_BLOCKS, SCAN_TPB>>>(vorder, adj);

    viol_kernel<<<(NV * DV + 255) / 256, 256>>>(adj);

    float* outF = (float*)d_out;
    if (out_size >= NV)
        colors_out_kernel<<<(NV + 255) / 256, 256>>>(outF);
    int mode = (out_size >= NV + 1) ? 0 : ((out_size < NV) ? 1 : 2);
    if (mode != 2)
        final_kernel<<<1, 1024>>>(outF, mode);
}